// round 16
// baseline (speedup 1.0000x reference)
#include <cuda_runtime.h>
#include <cuda_fp16.h>
#include <cuda_bf16.h>
#include <stdint.h>

// ---------------- static scratch (no allocation allowed) ----------------
#define N_MAX 100352          // >= N=100000 (+1 dummy zero row)
#define E_MAX 2200000         // >= E + 3*N (CSR padding to multiple of 4)
#define F 128                 // feature dim
#define SA 136                // padded smem row stride (halves)
#define PREP_BLOCKS 128
#define PREP_THREADS 1024

__device__ __align__(16) static __half g_t1[(size_t)N_MAX * F];  // (x@W1)*dis (fp16)
__device__ __align__(16) static __half g_h1[(size_t)N_MAX * F];  // relu layer-1 out (fp16)
__device__ __align__(16) static __half g_t2[(size_t)N_MAX * F];  // (h1@W2)*dis (fp16)
__device__ __align__(16) static __half g_w1t[F * F];             // W1^T fp16 [n][k]
__device__ __align__(16) static __half g_w2t[F * F];             // W2^T fp16 [n][k]
__device__ __align__(16) static float g_dis[N_MAX];
__device__ static int   g_degc[N_MAX];
__device__ static int   g_rowptr[N_MAX + 4];     // PADDED offsets (multiples of 4)
__device__ static int   g_rank[E_MAX];
__device__ __align__(16) static int g_csr[E_MAX];
__device__ static int   g_part[PREP_BLOCKS];
__device__ static int   g_gstart[1024];
__device__ static int   g_gend[1024];
__device__ static float g_inv[1024];
__device__ static int   g_e64;
__device__ static int   g_b64;
__device__ static int   g_bar_cnt[8];
__device__ static int   g_bar_gen[8];

// ---------------- software grid barrier (all blocks co-resident) ----------
__device__ __forceinline__ void gbar(int slot, int nblk) {
    __syncthreads();
    if (threadIdx.x == 0) {
        __threadfence();
        int gen = atomicAdd(&g_bar_gen[slot], 0);
        if (atomicAdd(&g_bar_cnt[slot], 1) == nblk - 1) {
            atomicExch(&g_bar_cnt[slot], 0);
            __threadfence();
            atomicAdd(&g_bar_gen[slot], 1);
        } else {
            while (atomicAdd(&g_bar_gen[slot], 0) == gen) {}
        }
        __threadfence();
    }
    __syncthreads();
}

__device__ __forceinline__ long long load_idx(const void* p, long long i, int is64) {
    if (is64) return ((const long long*)p)[i];
    return (long long)((const int*)p)[i];
}

__device__ __forceinline__ void load_pair(const void* p, long long i, int is64,
                                          int& v0, int& v1) {
    if (is64) {
        longlong2 v = ((const longlong2*)p)[i >> 1];
        v0 = (int)v.x; v1 = (int)v.y;
    } else {
        int2 v = ((const int2*)p)[i >> 1];
        v0 = v.x; v1 = v.y;
    }
}

// ---------------- kernel 1: ALL preprocessing (persistent, merged) ---------
__global__ void __launch_bounds__(PREP_THREADS) prep_kernel(
    const void* __restrict__ edge, const void* __restrict__ batch,
    const float* __restrict__ W1, const float* __restrict__ W2,
    float* __restrict__ out, int outw, int n, int E, int zrow)
{
    const int T = PREP_BLOCKS * PREP_THREADS;
    int t = threadIdx.x;
    int tid = blockIdx.x * PREP_THREADS + t;

    // ---- phase 0: dtype detect + W transpose + zero ----
    if (blockIdx.x < 2) {
        __shared__ int any;
        if (t == 0) any = 0;
        __syncthreads();
        const int* a = (blockIdx.x == 0) ? (const int*)edge : (const int*)batch;
        int local = 0;
        for (int i = 1 + 2 * t; i < 2048; i += 2 * PREP_THREADS) local |= a[i];
        if (local) atomicOr(&any, 1);
        __syncthreads();
        if (t == 0) {
            int is64 = (any == 0) ? 1 : 0;
            if (blockIdx.x == 0) g_e64 = is64; else g_b64 = is64;
        }
    }
    if (blockIdx.x == 2) {
        for (int i = t; i < F * F; i += PREP_THREADS) {
            int k = i >> 7, nn = i & 127;
            g_w1t[nn * F + k] = __float2half(W1[i]);
        }
    }
    if (blockIdx.x == 3) {
        for (int i = t; i < F * F; i += PREP_THREADS) {
            int k = i >> 7, nn = i & 127;
            g_w2t[nn * F + k] = __float2half(W2[i]);
        }
    }
    if (blockIdx.x == 4) {
        for (int i = t; i < F / 2; i += PREP_THREADS) {
            ((uint32_t*)(g_t1 + (size_t)n * F))[i] = 0u;
            ((uint32_t*)(g_t2 + (size_t)n * F))[i] = 0u;
        }
    }
    for (int i = tid; i < n; i += T) g_degc[i] = 0;
    for (int i = tid; i < outw; i += T) out[i] = 0.f;
    for (int i = tid; i < 1024; i += T) { g_gstart[i] = 0; g_gend[i] = 0; }
    gbar(0, PREP_BLOCKS);

    // ---- phase 1: degree histogram + rank + graph bounds ----
    {
        int is64 = g_e64;
        int epairs = (E + 1) / 2;
        bool even = ((E & 1) == 0);
        for (int p = tid; p < epairs; p += T) {
            int e0 = 2 * p;
            if (even || e0 + 1 < E) {
                int d0, d1;
                load_pair(edge, (long long)E + e0, is64, d0, d1);
                g_rank[e0]     = atomicAdd(&g_degc[d0], 1);
                g_rank[e0 + 1] = atomicAdd(&g_degc[d1], 1);
            } else {
                int d0 = (int)load_idx(edge, (long long)E + e0, is64);
                g_rank[e0] = atomicAdd(&g_degc[d0], 1);
            }
        }
        int is64b = g_b64;
        for (int i = tid; i < n; i += T) {
            int b = (int)load_idx(batch, i, is64b);
            int prev = (i > 0) ? (int)load_idx(batch, (long long)i - 1, is64b) : -1;
            int next = (i + 1 < n) ? (int)load_idx(batch, (long long)i + 1, is64b) : -2;
            if (b != prev) g_gstart[b] = i;
            if (b != next) g_gend[b] = i + 1;
        }
    }
    gbar(1, PREP_BLOCKS);

    // ---- phase 2: block-local scan of PADDED degrees + dis + inv ----
    if (blockIdx.x == PREP_BLOCKS - 1 && t < 1024) {
        int c = g_gend[t] - g_gstart[t];
        g_inv[t] = 1.f / (float)max(c, 1);
    }
    {
        __shared__ int sh[PREP_THREADS];
        int i = tid;
        int v = (i < n) ? g_degc[i] : 0;
        int pv = (v + 3) & ~3;                          // pad to multiple of 4
        if (i < n) g_dis[i] = rsqrtf((float)(v + 1));   // +1 self loop
        sh[t] = pv;
        __syncthreads();
        for (int off = 1; off < PREP_THREADS; off <<= 1) {
            int tmp = (t >= off) ? sh[t - off] : 0;
            __syncthreads();
            sh[t] += tmp;
            __syncthreads();
        }
        if (i < n) g_rowptr[i] = sh[t] - pv;
        if (t == PREP_THREADS - 1) g_part[blockIdx.x] = sh[PREP_THREADS - 1];
    }
    gbar(2, PREP_BLOCKS);

    // ---- phase 3: block 0 scans partials ----
    if (blockIdx.x == 0) {
        __shared__ int sp[PREP_BLOCKS];
        int v = (t < PREP_BLOCKS) ? g_part[t] : 0;
        if (t < PREP_BLOCKS) sp[t] = v;
        __syncthreads();
        for (int off = 1; off < PREP_BLOCKS; off <<= 1) {
            int tmp = (t < PREP_BLOCKS && t >= off) ? sp[t - off] : 0;
            __syncthreads();
            if (t < PREP_BLOCKS) sp[t] += tmp;
            __syncthreads();
        }
        if (t < PREP_BLOCKS) g_part[t] = sp[t] - v;
    }
    gbar(3, PREP_BLOCKS);

    // ---- phase 4: add block offsets ----
    {
        int i = tid;
        if (i < n) {
            int r = g_rowptr[i] + g_part[blockIdx.x];
            g_rowptr[i] = r;
            if (i == n - 1) g_rowptr[n] = r + ((g_degc[i] + 3) & ~3);
        }
    }
    gbar(4, PREP_BLOCKS);

    // ---- phase 5: CSR fill (atomic-free) + padding fill ----
    {
        int is64 = g_e64;
        int epairs = (E + 1) / 2;
        bool even = ((E & 1) == 0);
        for (int p = tid; p < epairs; p += T) {
            int e0 = 2 * p;
            if (even || e0 + 1 < E) {
                int s0, s1, d0, d1;
                load_pair(edge, (long long)e0, is64, s0, s1);
                load_pair(edge, (long long)E + e0, is64, d0, d1);
                int2 rk = *(const int2*)&g_rank[e0];
                g_csr[g_rowptr[d0] + rk.x] = s0;
                g_csr[g_rowptr[d1] + rk.y] = s1;
            } else {
                int s0 = (int)load_idx(edge, (long long)e0, is64);
                int d0 = (int)load_idx(edge, (long long)E + e0, is64);
                g_csr[g_rowptr[d0] + g_rank[e0]] = s0;
            }
        }
        for (int i = tid; i < n; i += T) {
            int st = g_rowptr[i];
            int deg = g_degc[i];
            int pdeg = (deg + 3) & ~3;
            for (int j = deg; j < pdeg; j++) g_csr[st + j] = zrow;
        }
    }
}

// ---------------- tensor-core GEMM: C = fp16((A @ W) * dis[row]) -----------
template<bool A_IS_HALF>
__global__ void __launch_bounds__(512) gemm_mma_kernel(
    const void* __restrict__ Aptr, const __half* __restrict__ Wt_g,
    __half* __restrict__ C, int n)
{
    extern __shared__ __half sh[];
    __half* As = sh;                 // [128][SA]
    __half* Wt = sh + 128 * SA;      // [128][SA], Wt[n][k]

    int t = threadIdx.x;
    int row0 = blockIdx.x * 128;

    for (int i = t; i < F * F / 8; i += 512) {
        int r = i >> 4, c16 = i & 15;
        *(uint4*)&Wt[r * SA + c16 * 8] = ((const uint4*)Wt_g)[i];
    }

    if (A_IS_HALF) {
        const __half* A = (const __half*)Aptr;
        for (int i = t; i < 128 * F / 8; i += 512) {
            int lin = i * 8;
            int r = lin >> 7, c = lin & 127;
            uint4 v = make_uint4(0u, 0u, 0u, 0u);
            if (row0 + r < n) v = *(const uint4*)&A[(size_t)(row0 + r) * F + c];
            *(uint4*)&As[r * SA + c] = v;
        }
    } else {
        const float* A = (const float*)Aptr;
        for (int i = t; i < 128 * F / 4; i += 512) {
            int lin = i * 4;
            int r = lin >> 7, c = lin & 127;
            float4 v = make_float4(0.f, 0.f, 0.f, 0.f);
            if (row0 + r < n) v = *(const float4*)&A[(size_t)(row0 + r) * F + c];
            *(__half2*)&As[r * SA + c]     = __floats2half2_rn(v.x, v.y);
            *(__half2*)&As[r * SA + c + 2] = __floats2half2_rn(v.z, v.w);
        }
    }
    __syncthreads();

    int w = t >> 5, lane = t & 31;
    int wm = w >> 1, wn = w & 1;
    int gq = lane >> 2, tq = lane & 3;
    int m0 = wm * 16;
    int n0 = wn * 64;

    float acc[8][4];
#pragma unroll
    for (int nt = 0; nt < 8; nt++)
#pragma unroll
        for (int c = 0; c < 4; c++) acc[nt][c] = 0.f;

#pragma unroll
    for (int k0 = 0; k0 < F; k0 += 16) {
        uint32_t a0 = *(const uint32_t*)&As[(m0 + gq) * SA + k0 + tq * 2];
        uint32_t a1 = *(const uint32_t*)&As[(m0 + gq + 8) * SA + k0 + tq * 2];
        uint32_t a2 = *(const uint32_t*)&As[(m0 + gq) * SA + k0 + tq * 2 + 8];
        uint32_t a3 = *(const uint32_t*)&As[(m0 + gq + 8) * SA + k0 + tq * 2 + 8];
#pragma unroll
        for (int nt = 0; nt < 8; nt++) {
            uint32_t b0 = *(const uint32_t*)&Wt[(n0 + nt * 8 + gq) * SA + k0 + tq * 2];
            uint32_t b1 = *(const uint32_t*)&Wt[(n0 + nt * 8 + gq) * SA + k0 + tq * 2 + 8];
            asm volatile(
                "mma.sync.aligned.m16n8k16.row.col.f32.f16.f16.f32 "
                "{%0,%1,%2,%3}, {%4,%5,%6,%7}, {%8,%9}, {%0,%1,%2,%3};"
                : "+f"(acc[nt][0]), "+f"(acc[nt][1]), "+f"(acc[nt][2]), "+f"(acc[nt][3])
                : "r"(a0), "r"(a1), "r"(a2), "r"(a3), "r"(b0), "r"(b1));
        }
    }

    int r1 = row0 + m0 + gq;
    int r2 = r1 + 8;
    float d1 = (r1 < n) ? g_dis[r1] : 0.f;
    float d2 = (r2 < n) ? g_dis[r2] : 0.f;
#pragma unroll
    for (int nt = 0; nt < 8; nt++) {
        int col = n0 + nt * 8 + tq * 2;
        if (r1 < n) *(__half2*)&C[(size_t)r1 * F + col] = __floats2half2_rn(acc[nt][0] * d1, acc[nt][1] * d1);
        if (r2 < n) *(__half2*)&C[(size_t)r2 * F + col] = __floats2half2_rn(acc[nt][2] * d2, acc[nt][3] * d2);
    }
}

// ---------------- CSR gather: 16-lane group/node, uint4/lane, fp16 tree ----
// s[8] += elements of u (converted)
__device__ __forceinline__ void cvt_add8(float* s, uint4 u) {
    const __half2* h = (const __half2*)&u;
#pragma unroll
    for (int j = 0; j < 4; j++) {
        float2 f = __half22float2(h[j]);
        s[2 * j]     += f.x;
        s[2 * j + 1] += f.y;
    }
}

// depth-3 fp16 tree over 8 gathered uint4 rows -> s[8]
__device__ __forceinline__ void acco16(float* s,
                                       uint4 u0, uint4 u1, uint4 u2, uint4 u3,
                                       uint4 u4, uint4 u5, uint4 u6, uint4 u7) {
    const __half2 *h0 = (const __half2*)&u0, *h1 = (const __half2*)&u1;
    const __half2 *h2 = (const __half2*)&u2, *h3 = (const __half2*)&u3;
    const __half2 *h4 = (const __half2*)&u4, *h5 = (const __half2*)&u5;
    const __half2 *h6 = (const __half2*)&u6, *h7 = (const __half2*)&u7;
#pragma unroll
    for (int j = 0; j < 4; j++) {
        __half2 p0 = __hadd2(h0[j], h1[j]);
        __half2 p1 = __hadd2(h2[j], h3[j]);
        __half2 p2 = __hadd2(h4[j], h5[j]);
        __half2 p3 = __hadd2(h6[j], h7[j]);
        __half2 q0 = __hadd2(p0, p1);
        __half2 q1 = __hadd2(p2, p3);
        __half2 r  = __hadd2(q0, q1);
        float2 f = __half22float2(r);
        s[2 * j]     += f.x;
        s[2 * j + 1] += f.y;
    }
}

// depth-2 fp16 tree over 4 gathered uint4 rows -> s[8]
__device__ __forceinline__ void accq16(float* s,
                                       uint4 u0, uint4 u1, uint4 u2, uint4 u3) {
    const __half2 *h0 = (const __half2*)&u0, *h1 = (const __half2*)&u1;
    const __half2 *h2 = (const __half2*)&u2, *h3 = (const __half2*)&u3;
#pragma unroll
    for (int j = 0; j < 4; j++) {
        __half2 p0 = __hadd2(h0[j], h1[j]);
        __half2 p1 = __hadd2(h2[j], h3[j]);
        __half2 r  = __hadd2(p0, p1);
        float2 f = __half22float2(r);
        s[2 * j]     += f.x;
        s[2 * j + 1] += f.y;
    }
}

__device__ __forceinline__ void agg_row16(const uint4* __restrict__ gp,
                                          int node, int l, float* s) {
#pragma unroll
    for (int j = 0; j < 8; j++) s[j] = 0.f;
    cvt_add8(s, __ldg(&gp[(size_t)node * 16 + l]));   // self loop (pre-scaled)
    int i = g_rowptr[node];
    int end = g_rowptr[node + 1];                     // padded: (end-i) % 4 == 0
    for (; i + 8 <= end; i += 8) {
        int4 ia = __ldg((const int4*)&g_csr[i]);
        int4 ib = __ldg((const int4*)&g_csr[i + 4]);
        uint4 u0 = __ldg(&gp[(size_t)ia.x * 16 + l]);
        uint4 u1 = __ldg(&gp[(size_t)ia.y * 16 + l]);
        uint4 u2 = __ldg(&gp[(size_t)ia.z * 16 + l]);
        uint4 u3 = __ldg(&gp[(size_t)ia.w * 16 + l]);
        uint4 u4 = __ldg(&gp[(size_t)ib.x * 16 + l]);
        uint4 u5 = __ldg(&gp[(size_t)ib.y * 16 + l]);
        uint4 u6 = __ldg(&gp[(size_t)ib.z * 16 + l]);
        uint4 u7 = __ldg(&gp[(size_t)ib.w * 16 + l]);
        acco16(s, u0, u1, u2, u3, u4, u5, u6, u7);
    }
    if (i < end) {                                    // exactly one 4-block
        int4 ia = __ldg((const int4*)&g_csr[i]);
        uint4 u0 = __ldg(&gp[(size_t)ia.x * 16 + l]);
        uint4 u1 = __ldg(&gp[(size_t)ia.y * 16 + l]);
        uint4 u2 = __ldg(&gp[(size_t)ia.z * 16 + l]);
        uint4 u3 = __ldg(&gp[(size_t)ia.w * 16 + l]);
        accq16(s, u0, u1, u2, u3);
    }
}

// h1 = fp16(relu(dis*sum + b)); 16-lane group per node
__global__ void __launch_bounds__(256) agg1_kernel(const float* __restrict__ b, int n) {
    int grp = (blockIdx.x * blockDim.x + threadIdx.x) >> 4;
    int l = threadIdx.x & 15;
    if (grp >= n) return;
    float s[8];
    agg_row16((const uint4*)g_t1, grp, l, s);
    float d = g_dis[grp];
    float4 b0 = __ldg((const float4*)&b[l * 8]);
    float4 b1 = __ldg((const float4*)&b[l * 8 + 4]);
    float o0 = fmaxf(fmaf(d, s[0], b0.x), 0.f);
    float o1 = fmaxf(fmaf(d, s[1], b0.y), 0.f);
    float o2 = fmaxf(fmaf(d, s[2], b0.z), 0.f);
    float o3 = fmaxf(fmaf(d, s[3], b0.w), 0.f);
    float o4 = fmaxf(fmaf(d, s[4], b1.x), 0.f);
    float o5 = fmaxf(fmaf(d, s[5], b1.y), 0.f);
    float o6 = fmaxf(fmaf(d, s[6], b1.z), 0.f);
    float o7 = fmaxf(fmaf(d, s[7], b1.w), 0.f);
    __half2 p0 = __floats2half2_rn(o0, o1);
    __half2 p1 = __floats2half2_rn(o2, o3);
    __half2 p2 = __floats2half2_rn(o4, o5);
    __half2 p3 = __floats2half2_rn(o6, o7);
    uint4 st;
    st.x = *(uint32_t*)&p0; st.y = *(uint32_t*)&p1;
    st.z = *(uint32_t*)&p2; st.w = *(uint32_t*)&p3;
    ((uint4*)g_h1)[(size_t)grp * 16 + l] = st;
}

// o = relu(dis*sum + b) * inv_count; mean-pool scatter
__global__ void __launch_bounds__(256) agg2_kernel(
    const void* __restrict__ batch, const float* __restrict__ b,
    float* __restrict__ out, int n)
{
    int grp = (blockIdx.x * blockDim.x + threadIdx.x) >> 4;
    int l = threadIdx.x & 15;
    if (grp >= n) return;
    float s[8];
    agg_row16((const uint4*)g_t2, grp, l, s);
    float d = g_dis[grp];
    float4 b0 = __ldg((const float4*)&b[l * 8]);
    float4 b1 = __ldg((const float4*)&b[l * 8 + 4]);
    long long gid = load_idx(batch, grp, g_b64);
    float inv = __ldg(&g_inv[gid]);
    float o0 = fmaxf(fmaf(d, s[0], b0.x), 0.f) * inv;
    float o1 = fmaxf(fmaf(d, s[1], b0.y), 0.f) * inv;
    float o2 = fmaxf(fmaf(d, s[2], b0.z), 0.f) * inv;
    float o3 = fmaxf(fmaf(d, s[3], b0.w), 0.f) * inv;
    float o4 = fmaxf(fmaf(d, s[4], b1.x), 0.f) * inv;
    float o5 = fmaxf(fmaf(d, s[5], b1.y), 0.f) * inv;
    float o6 = fmaxf(fmaf(d, s[6], b1.z), 0.f) * inv;
    float o7 = fmaxf(fmaf(d, s[7], b1.w), 0.f) * inv;
    float* p = &out[(size_t)gid * F + l * 8];
    asm volatile("red.global.add.v4.f32 [%0], {%1,%2,%3,%4};"
                 :: "l"(p), "f"(o0), "f"(o1), "f"(o2), "f"(o3) : "memory");
    asm volatile("red.global.add.v4.f32 [%0], {%1,%2,%3,%4};"
                 :: "l"(p + 4), "f"(o4), "f"(o5), "f"(o6), "f"(o7) : "memory");
}

// ---------------- launch ----------------
extern "C" void kernel_launch(void* const* d_in, const int* in_sizes, int n_in,
                              void* d_out, int out_size) {
    const float* x    = (const float*)d_in[0];
    const void*  edge = d_in[1];
    const void*  batch= d_in[2];
    const float* W1   = (const float*)d_in[3];
    const float* b1   = (const float*)d_in[4];
    const float* W2   = (const float*)d_in[5];
    const float* b2   = (const float*)d_in[6];
    float* out = (float*)d_out;

    int N = in_sizes[0] / F;
    int E = in_sizes[1] / 2;
    int G = out_size / F;

    void *p_t1, *p_h1, *p_t2, *p_w1t, *p_w2t;
    cudaGetSymbolAddress(&p_t1, g_t1);
    cudaGetSymbolAddress(&p_h1, g_h1);
    cudaGetSymbolAddress(&p_t2, g_t2);
    cudaGetSymbolAddress(&p_w1t, g_w1t);
    cudaGetSymbolAddress(&p_w2t, g_w2t);

    const int SMEM = 2 * 128 * SA * (int)sizeof(__half);   // 69632 bytes
    cudaFuncSetAttribute(gemm_mma_kernel<false>, cudaFuncAttributeMaxDynamicSharedMemorySize, SMEM);
    cudaFuncSetAttribute(gemm_mma_kernel<true>,  cudaFuncAttributeMaxDynamicSharedMemorySize, SMEM);

    const int TB = 256;
    int gemm_grid = (N + 127) / 128;
    int agg_grid = (N + 15) / 16;      // 16 nodes per 256-thread block

    // launches: 0 prep, 1 gemm1, 2 agg1, 3 gemm2 (profiled slot), 4 agg2
    prep_kernel<<<PREP_BLOCKS, PREP_THREADS>>>(edge, batch, W1, W2, out, G * F, N, E, N);
    gemm_mma_kernel<false><<<gemm_grid, 512, SMEM>>>(x, (const __half*)p_w1t, (__half*)p_t1, N);
    agg1_kernel<<<agg_grid, TB>>>(b1, N);
    gemm_mma_kernel<true><<<gemm_grid, 512, SMEM>>>(p_h1, (const __half*)p_w2t, (__half*)p_t2, N);
    agg2_kernel<<<agg_grid, TB>>>(batch, b2, out, N);
}

// round 17
// speedup vs baseline: 1.0750x; 1.0750x over previous
#include <cuda_runtime.h>
#include <cuda_fp16.h>
#include <cuda_bf16.h>
#include <stdint.h>

// ---------------- static scratch (no allocation allowed) ----------------
#define N_MAX 100352          // >= N=100000 (+1 dummy zero row)
#define E_MAX 2200000         // >= E + 3*N (CSR padding to multiple of 4)
#define F 128                 // feature dim
#define SA 136                // padded smem row stride (halves)
#define PREP_BLOCKS 128
#define PREP_THREADS 1024

__device__ __align__(16) static __half g_t1[(size_t)N_MAX * F];  // (x@W1)*dis (fp16)
__device__ __align__(16) static __half g_h1[(size_t)N_MAX * F];  // relu layer-1 out (fp16)
__device__ __align__(16) static __half g_t2[(size_t)N_MAX * F];  // (h1@W2)*dis (fp16)
__device__ __align__(16) static __half g_w1t[F * F];             // W1^T fp16 [n][k]
__device__ __align__(16) static __half g_w2t[F * F];             // W2^T fp16 [n][k]
__device__ __align__(16) static float g_dis[N_MAX];
__device__ static int   g_degc[N_MAX];
__device__ static int   g_rowptr[N_MAX + 4];     // PADDED offsets (multiples of 4)
__device__ static int   g_rank[E_MAX];
__device__ __align__(16) static int g_csr[E_MAX];
__device__ static int   g_part[PREP_BLOCKS];
__device__ static int   g_gstart[1024];
__device__ static int   g_gend[1024];
__device__ static float g_inv[1024];
__device__ static int   g_e64;
__device__ static int   g_b64;
__device__ static int   g_bar_cnt[8];
__device__ static int   g_bar_gen[8];

// ---------------- software grid barrier (all blocks co-resident) ----------
__device__ __forceinline__ void gbar(int slot, int nblk) {
    __syncthreads();
    if (threadIdx.x == 0) {
        __threadfence();
        int gen = atomicAdd(&g_bar_gen[slot], 0);
        if (atomicAdd(&g_bar_cnt[slot], 1) == nblk - 1) {
            atomicExch(&g_bar_cnt[slot], 0);
            __threadfence();
            atomicAdd(&g_bar_gen[slot], 1);
        } else {
            while (atomicAdd(&g_bar_gen[slot], 0) == gen) {}
        }
        __threadfence();
    }
    __syncthreads();
}

__device__ __forceinline__ long long load_idx(const void* p, long long i, int is64) {
    if (is64) return ((const long long*)p)[i];
    return (long long)((const int*)p)[i];
}

__device__ __forceinline__ void load_pair(const void* p, long long i, int is64,
                                          int& v0, int& v1) {
    if (is64) {
        longlong2 v = ((const longlong2*)p)[i >> 1];
        v0 = (int)v.x; v1 = (int)v.y;
    } else {
        int2 v = ((const int2*)p)[i >> 1];
        v0 = v.x; v1 = v.y;
    }
}

// ---------------- kernel 1: ALL preprocessing (persistent, merged) ---------
__global__ void __launch_bounds__(PREP_THREADS) prep_kernel(
    const void* __restrict__ edge, const void* __restrict__ batch,
    const float* __restrict__ W1, const float* __restrict__ W2,
    float* __restrict__ out, int outw, int n, int E, int zrow)
{
    const int T = PREP_BLOCKS * PREP_THREADS;
    int t = threadIdx.x;
    int tid = blockIdx.x * PREP_THREADS + t;

    // ---- phase 0: dtype detect + W transpose + zero ----
    if (blockIdx.x < 2) {
        __shared__ int any;
        if (t == 0) any = 0;
        __syncthreads();
        const int* a = (blockIdx.x == 0) ? (const int*)edge : (const int*)batch;
        int local = 0;
        for (int i = 1 + 2 * t; i < 2048; i += 2 * PREP_THREADS) local |= a[i];
        if (local) atomicOr(&any, 1);
        __syncthreads();
        if (t == 0) {
            int is64 = (any == 0) ? 1 : 0;
            if (blockIdx.x == 0) g_e64 = is64; else g_b64 = is64;
        }
    }
    if (blockIdx.x == 2) {
        for (int i = t; i < F * F; i += PREP_THREADS) {
            int k = i >> 7, nn = i & 127;
            g_w1t[nn * F + k] = __float2half(W1[i]);
        }
    }
    if (blockIdx.x == 3) {
        for (int i = t; i < F * F; i += PREP_THREADS) {
            int k = i >> 7, nn = i & 127;
            g_w2t[nn * F + k] = __float2half(W2[i]);
        }
    }
    if (blockIdx.x == 4) {
        for (int i = t; i < F / 2; i += PREP_THREADS) {
            ((uint32_t*)(g_t1 + (size_t)n * F))[i] = 0u;
            ((uint32_t*)(g_t2 + (size_t)n * F))[i] = 0u;
        }
    }
    for (int i = tid; i < n; i += T) g_degc[i] = 0;
    for (int i = tid; i < outw; i += T) out[i] = 0.f;
    for (int i = tid; i < 1024; i += T) { g_gstart[i] = 0; g_gend[i] = 0; }
    gbar(0, PREP_BLOCKS);

    // ---- phase 1: degree histogram + rank + graph bounds ----
    {
        int is64 = g_e64;
        int epairs = (E + 1) / 2;
        bool even = ((E & 1) == 0);
        for (int p = tid; p < epairs; p += T) {
            int e0 = 2 * p;
            if (even || e0 + 1 < E) {
                int d0, d1;
                load_pair(edge, (long long)E + e0, is64, d0, d1);
                g_rank[e0]     = atomicAdd(&g_degc[d0], 1);
                g_rank[e0 + 1] = atomicAdd(&g_degc[d1], 1);
            } else {
                int d0 = (int)load_idx(edge, (long long)E + e0, is64);
                g_rank[e0] = atomicAdd(&g_degc[d0], 1);
            }
        }
        int is64b = g_b64;
        for (int i = tid; i < n; i += T) {
            int b = (int)load_idx(batch, i, is64b);
            int prev = (i > 0) ? (int)load_idx(batch, (long long)i - 1, is64b) : -1;
            int next = (i + 1 < n) ? (int)load_idx(batch, (long long)i + 1, is64b) : -2;
            if (b != prev) g_gstart[b] = i;
            if (b != next) g_gend[b] = i + 1;
        }
    }
    gbar(1, PREP_BLOCKS);

    // ---- phase 2: block-local scan of PADDED degrees + dis + inv ----
    if (blockIdx.x == PREP_BLOCKS - 1 && t < 1024) {
        int c = g_gend[t] - g_gstart[t];
        g_inv[t] = 1.f / (float)max(c, 1);
    }
    {
        __shared__ int sh[PREP_THREADS];
        int i = tid;
        int v = (i < n) ? g_degc[i] : 0;
        int pv = (v + 3) & ~3;                          // pad to multiple of 4
        if (i < n) g_dis[i] = rsqrtf((float)(v + 1));   // +1 self loop
        sh[t] = pv;
        __syncthreads();
        for (int off = 1; off < PREP_THREADS; off <<= 1) {
            int tmp = (t >= off) ? sh[t - off] : 0;
            __syncthreads();
            sh[t] += tmp;
            __syncthreads();
        }
        if (i < n) g_rowptr[i] = sh[t] - pv;
        if (t == PREP_THREADS - 1) g_part[blockIdx.x] = sh[PREP_THREADS - 1];
    }
    gbar(2, PREP_BLOCKS);

    // ---- phase 3: block 0 scans partials ----
    if (blockIdx.x == 0) {
        __shared__ int sp[PREP_BLOCKS];
        int v = (t < PREP_BLOCKS) ? g_part[t] : 0;
        if (t < PREP_BLOCKS) sp[t] = v;
        __syncthreads();
        for (int off = 1; off < PREP_BLOCKS; off <<= 1) {
            int tmp = (t < PREP_BLOCKS && t >= off) ? sp[t - off] : 0;
            __syncthreads();
            if (t < PREP_BLOCKS) sp[t] += tmp;
            __syncthreads();
        }
        if (t < PREP_BLOCKS) g_part[t] = sp[t] - v;
    }
    gbar(3, PREP_BLOCKS);

    // ---- phase 4: add block offsets ----
    {
        int i = tid;
        if (i < n) {
            int r = g_rowptr[i] + g_part[blockIdx.x];
            g_rowptr[i] = r;
            if (i == n - 1) g_rowptr[n] = r + ((g_degc[i] + 3) & ~3);
        }
    }
    gbar(4, PREP_BLOCKS);

    // ---- phase 5: CSR fill (atomic-free) + padding fill ----
    {
        int is64 = g_e64;
        int epairs = (E + 1) / 2;
        bool even = ((E & 1) == 0);
        for (int p = tid; p < epairs; p += T) {
            int e0 = 2 * p;
            if (even || e0 + 1 < E) {
                int s0, s1, d0, d1;
                load_pair(edge, (long long)e0, is64, s0, s1);
                load_pair(edge, (long long)E + e0, is64, d0, d1);
                int2 rk = *(const int2*)&g_rank[e0];
                g_csr[g_rowptr[d0] + rk.x] = s0;
                g_csr[g_rowptr[d1] + rk.y] = s1;
            } else {
                int s0 = (int)load_idx(edge, (long long)e0, is64);
                int d0 = (int)load_idx(edge, (long long)E + e0, is64);
                g_csr[g_rowptr[d0] + g_rank[e0]] = s0;
            }
        }
        for (int i = tid; i < n; i += T) {
            int st = g_rowptr[i];
            int deg = g_degc[i];
            int pdeg = (deg + 3) & ~3;
            for (int j = deg; j < pdeg; j++) g_csr[st + j] = zrow;
        }
    }
}

// ---------------- tensor-core GEMM v2: A from global, Wt in smem ----------
// 512 threads (16 warps). tile 128x128. warp (wm,wn): rows wm*16..+16, cols wn*64..+64.
// A fragments loaded directly from global (per-warp rows, no reuse -> no staging).
template<bool A_IS_HALF>
__global__ void __launch_bounds__(512) gemm_mma_kernel(
    const void* __restrict__ Aptr, const __half* __restrict__ Wt_g,
    __half* __restrict__ C, int n)
{
    extern __shared__ __half sh[];
    __half* Wt = sh;                 // [128][SA], Wt[n][k]

    int t = threadIdx.x;
    int row0 = blockIdx.x * 128;

    // stage Wt (fp16, coalesced uint4 copy with pad)
    for (int i = t; i < F * F / 8; i += 512) {
        int r = i >> 4, c16 = i & 15;
        *(uint4*)&Wt[r * SA + c16 * 8] = ((const uint4*)Wt_g)[i];
    }
    __syncthreads();

    int w = t >> 5, lane = t & 31;
    int wm = w >> 1, wn = w & 1;
    int gq = lane >> 2, tq = lane & 3;
    int m0 = wm * 16;
    int n0 = wn * 64;

    int r1 = row0 + m0 + gq;
    int r2 = r1 + 8;
    bool v1 = (r1 < n), v2 = (r2 < n);

    float acc[8][4];
#pragma unroll
    for (int nt = 0; nt < 8; nt++)
#pragma unroll
        for (int c = 0; c < 4; c++) acc[nt][c] = 0.f;

#pragma unroll
    for (int k0 = 0; k0 < F; k0 += 16) {
        uint32_t a0, a1, a2, a3;
        if (A_IS_HALF) {
            const __half* A = (const __half*)Aptr;
            a0 = v1 ? *(const uint32_t*)&A[(size_t)r1 * F + k0 + tq * 2] : 0u;
            a1 = v2 ? *(const uint32_t*)&A[(size_t)r2 * F + k0 + tq * 2] : 0u;
            a2 = v1 ? *(const uint32_t*)&A[(size_t)r1 * F + k0 + tq * 2 + 8] : 0u;
            a3 = v2 ? *(const uint32_t*)&A[(size_t)r2 * F + k0 + tq * 2 + 8] : 0u;
        } else {
            const float* A = (const float*)Aptr;
            float2 f0 = v1 ? *(const float2*)&A[(size_t)r1 * F + k0 + tq * 2] : make_float2(0.f, 0.f);
            float2 f1 = v2 ? *(const float2*)&A[(size_t)r2 * F + k0 + tq * 2] : make_float2(0.f, 0.f);
            float2 f2 = v1 ? *(const float2*)&A[(size_t)r1 * F + k0 + tq * 2 + 8] : make_float2(0.f, 0.f);
            float2 f3 = v2 ? *(const float2*)&A[(size_t)r2 * F + k0 + tq * 2 + 8] : make_float2(0.f, 0.f);
            __half2 h0 = __floats2half2_rn(f0.x, f0.y);
            __half2 h1 = __floats2half2_rn(f1.x, f1.y);
            __half2 h2 = __floats2half2_rn(f2.x, f2.y);
            __half2 h3 = __floats2half2_rn(f3.x, f3.y);
            a0 = *(uint32_t*)&h0; a1 = *(uint32_t*)&h1;
            a2 = *(uint32_t*)&h2; a3 = *(uint32_t*)&h3;
        }
#pragma unroll
        for (int nt = 0; nt < 8; nt++) {
            uint32_t b0 = *(const uint32_t*)&Wt[(n0 + nt * 8 + gq) * SA + k0 + tq * 2];
            uint32_t b1 = *(const uint32_t*)&Wt[(n0 + nt * 8 + gq) * SA + k0 + tq * 2 + 8];
            asm volatile(
                "mma.sync.aligned.m16n8k16.row.col.f32.f16.f16.f32 "
                "{%0,%1,%2,%3}, {%4,%5,%6,%7}, {%8,%9}, {%0,%1,%2,%3};"
                : "+f"(acc[nt][0]), "+f"(acc[nt][1]), "+f"(acc[nt][2]), "+f"(acc[nt][3])
                : "r"(a0), "r"(a1), "r"(a2), "r"(a3), "r"(b0), "r"(b1));
        }
    }

    float d1 = v1 ? g_dis[r1] : 0.f;
    float d2 = v2 ? g_dis[r2] : 0.f;
#pragma unroll
    for (int nt = 0; nt < 8; nt++) {
        int col = n0 + nt * 8 + tq * 2;
        if (v1) *(__half2*)&C[(size_t)r1 * F + col] = __floats2half2_rn(acc[nt][0] * d1, acc[nt][1] * d1);
        if (v2) *(__half2*)&C[(size_t)r2 * F + col] = __floats2half2_rn(acc[nt][2] * d2, acc[nt][3] * d2);
    }
}

// ---------------- CSR gather (warp/node, depth-3 fp16 tree, aligned) -------
__device__ __forceinline__ void acc2(float4& s, uint2 u) {
    float2 a = __half22float2(*(const __half2*)&u.x);
    float2 b = __half22float2(*(const __half2*)&u.y);
    s.x += a.x; s.y += a.y; s.z += b.x; s.w += b.y;
}

__device__ __forceinline__ void accq(float4& s, uint2 u0, uint2 u1, uint2 u2, uint2 u3) {
    __half2 ax = __hadd2(*(const __half2*)&u0.x, *(const __half2*)&u1.x);
    __half2 ay = __hadd2(*(const __half2*)&u0.y, *(const __half2*)&u1.y);
    __half2 bx = __hadd2(*(const __half2*)&u2.x, *(const __half2*)&u3.x);
    __half2 by = __hadd2(*(const __half2*)&u2.y, *(const __half2*)&u3.y);
    __half2 qx = __hadd2(ax, bx);
    __half2 qy = __hadd2(ay, by);
    float2 fx = __half22float2(qx);
    float2 fy = __half22float2(qy);
    s.x += fx.x; s.y += fx.y; s.z += fy.x; s.w += fy.y;
}

__device__ __forceinline__ void acco(float4& s,
                                     uint2 u0, uint2 u1, uint2 u2, uint2 u3,
                                     uint2 u4, uint2 u5, uint2 u6, uint2 u7) {
    __half2 p0x = __hadd2(*(const __half2*)&u0.x, *(const __half2*)&u1.x);
    __half2 p1x = __hadd2(*(const __half2*)&u2.x, *(const __half2*)&u3.x);
    __half2 p2x = __hadd2(*(const __half2*)&u4.x, *(const __half2*)&u5.x);
    __half2 p3x = __hadd2(*(const __half2*)&u6.x, *(const __half2*)&u7.x);
    __half2 p0y = __hadd2(*(const __half2*)&u0.y, *(const __half2*)&u1.y);
    __half2 p1y = __hadd2(*(const __half2*)&u2.y, *(const __half2*)&u3.y);
    __half2 p2y = __hadd2(*(const __half2*)&u4.y, *(const __half2*)&u5.y);
    __half2 p3y = __hadd2(*(const __half2*)&u6.y, *(const __half2*)&u7.y);
    __half2 q0x = __hadd2(p0x, p1x);
    __half2 q1x = __hadd2(p2x, p3x);
    __half2 q0y = __hadd2(p0y, p1y);
    __half2 q1y = __hadd2(p2y, p3y);
    __half2 rx = __hadd2(q0x, q1x);
    __half2 ry = __hadd2(q0y, q1y);
    float2 fx = __half22float2(rx);
    float2 fy = __half22float2(ry);
    s.x += fx.x; s.y += fx.y; s.z += fy.x; s.w += fy.y;
}

__device__ __forceinline__ float4 agg_row(const uint2* __restrict__ gp,
                                          int node, int lane) {
    float4 s = make_float4(0.f, 0.f, 0.f, 0.f);
    acc2(s, __ldg(&gp[(size_t)node * 32 + lane]));    // self loop (pre-scaled)
    int i = g_rowptr[node];
    int end = g_rowptr[node + 1];                     // padded: (end-i) % 4 == 0
    for (; i + 8 <= end; i += 8) {
        int4 ia = __ldg((const int4*)&g_csr[i]);
        int4 ib = __ldg((const int4*)&g_csr[i + 4]);
        uint2 u0 = __ldg(&gp[(size_t)ia.x * 32 + lane]);
        uint2 u1 = __ldg(&gp[(size_t)ia.y * 32 + lane]);
        uint2 u2 = __ldg(&gp[(size_t)ia.z * 32 + lane]);
        uint2 u3 = __ldg(&gp[(size_t)ia.w * 32 + lane]);
        uint2 u4 = __ldg(&gp[(size_t)ib.x * 32 + lane]);
        uint2 u5 = __ldg(&gp[(size_t)ib.y * 32 + lane]);
        uint2 u6 = __ldg(&gp[(size_t)ib.z * 32 + lane]);
        uint2 u7 = __ldg(&gp[(size_t)ib.w * 32 + lane]);
        acco(s, u0, u1, u2, u3, u4, u5, u6, u7);
    }
    if (i < end) {                                    // exactly one 4-block
        int4 ia = __ldg((const int4*)&g_csr[i]);
        uint2 u0 = __ldg(&gp[(size_t)ia.x * 32 + lane]);
        uint2 u1 = __ldg(&gp[(size_t)ia.y * 32 + lane]);
        uint2 u2 = __ldg(&gp[(size_t)ia.z * 32 + lane]);
        uint2 u3 = __ldg(&gp[(size_t)ia.w * 32 + lane]);
        accq(s, u0, u1, u2, u3);
    }
    return s;
}

// h1 = fp16(relu(dis*sum + b))
__global__ void __launch_bounds__(256) agg1_kernel(const float* __restrict__ b, int n) {
    int w = (blockIdx.x * blockDim.x + threadIdx.x) >> 5;
    int lane = threadIdx.x & 31;
    if (w >= n) return;
    float4 s = agg_row((const uint2*)g_t1, w, lane);
    float d = g_dis[w];
    float4 bb = __ldg((const float4*)&b[lane * 4]);
    float ox = fmaxf(fmaf(d, s.x, bb.x), 0.f);
    float oy = fmaxf(fmaf(d, s.y, bb.y), 0.f);
    float oz = fmaxf(fmaf(d, s.z, bb.z), 0.f);
    float ow = fmaxf(fmaf(d, s.w, bb.w), 0.f);
    __half2 p0 = __floats2half2_rn(ox, oy);
    __half2 p1 = __floats2half2_rn(oz, ow);
    uint2 st;
    st.x = *(uint32_t*)&p0;
    st.y = *(uint32_t*)&p1;
    ((uint2*)g_h1)[(size_t)w * 32 + lane] = st;
}

// o = relu(dis*sum + b) * inv_count; mean-pool scatter
__global__ void __launch_bounds__(256) agg2_kernel(
    const void* __restrict__ batch, const float* __restrict__ b,
    float* __restrict__ out, int n)
{
    int w = (blockIdx.x * blockDim.x + threadIdx.x) >> 5;
    int lane = threadIdx.x & 31;
    if (w >= n) return;
    float4 s = agg_row((const uint2*)g_t2, w, lane);
    float d = g_dis[w];
    float4 bb = __ldg((const float4*)&b[lane * 4]);
    long long gid = load_idx(batch, w, g_b64);
    float inv = __ldg(&g_inv[gid]);
    float ox = fmaxf(fmaf(d, s.x, bb.x), 0.f) * inv;
    float oy = fmaxf(fmaf(d, s.y, bb.y), 0.f) * inv;
    float oz = fmaxf(fmaf(d, s.z, bb.z), 0.f) * inv;
    float ow = fmaxf(fmaf(d, s.w, bb.w), 0.f) * inv;
    float* p = &out[(size_t)gid * F + lane * 4];
    asm volatile("red.global.add.v4.f32 [%0], {%1,%2,%3,%4};"
                 :: "l"(p), "f"(ox), "f"(oy), "f"(oz), "f"(ow) : "memory");
}

// ---------------- launch ----------------
extern "C" void kernel_launch(void* const* d_in, const int* in_sizes, int n_in,
                              void* d_out, int out_size) {
    const float* x    = (const float*)d_in[0];
    const void*  edge = d_in[1];
    const void*  batch= d_in[2];
    const float* W1   = (const float*)d_in[3];
    const float* b1   = (const float*)d_in[4];
    const float* W2   = (const float*)d_in[5];
    const float* b2   = (const float*)d_in[6];
    float* out = (float*)d_out;

    int N = in_sizes[0] / F;
    int E = in_sizes[1] / 2;
    int G = out_size / F;

    void *p_t1, *p_h1, *p_t2, *p_w1t, *p_w2t;
    cudaGetSymbolAddress(&p_t1, g_t1);
    cudaGetSymbolAddress(&p_h1, g_h1);
    cudaGetSymbolAddress(&p_t2, g_t2);
    cudaGetSymbolAddress(&p_w1t, g_w1t);
    cudaGetSymbolAddress(&p_w2t, g_w2t);

    const int SMEM = 128 * SA * (int)sizeof(__half);   // 34816 bytes (Wt only)
    cudaFuncSetAttribute(gemm_mma_kernel<false>, cudaFuncAttributeMaxDynamicSharedMemorySize, SMEM);
    cudaFuncSetAttribute(gemm_mma_kernel<true>,  cudaFuncAttributeMaxDynamicSharedMemorySize, SMEM);

    const int TB = 256;
    int gemm_grid = (N + 127) / 128;
    int agg_grid = (N + 7) / 8;

    // launches: 0 prep, 1 gemm1, 2 agg1, 3 gemm2, 4 agg2
    prep_kernel<<<PREP_BLOCKS, PREP_THREADS>>>(edge, batch, W1, W2, out, G * F, N, E, N);
    gemm_mma_kernel<false><<<gemm_grid, 512, SMEM>>>(x, (const __half*)p_w1t, (__half*)p_t1, N);
    agg1_kernel<<<agg_grid, TB>>>(b1, N);
    gemm_mma_kernel<true><<<gemm_grid, 512, SMEM>>>(p_h1, (const __half*)p_w2t, (__half*)p_t2, N);
    agg2_kernel<<<agg_grid, TB>>>(batch, b2, out, N);
}